// round 16
// baseline (speedup 1.0000x reference)
#include <cuda_runtime.h>
#include <cuda_bf16.h>
#include <cstdint>
#include <cstddef>

// Problem constants
#define BATCH   32
#define TSTEPS  2048
#define INDIM   256
#define HDIM    256
#define GDIM    768            // 3*H
#define OUTDIM  256

// Scratch for xg = x @ W_i + bias : (B*T, 3H) fp32 = 192 MB
__device__ float g_xg[(size_t)BATCH * TSTEPS * GDIM];

// ---------------------------------------------------------------------------
// Helpers
// ---------------------------------------------------------------------------
__device__ __forceinline__ uint32_t smem_u32(const void* p) {
    uint32_t a;
    asm("{ .reg .u64 t; cvta.to.shared.u64 t, %1; cvt.u32.u64 %0, t; }"
        : "=r"(a) : "l"(p));
    return a;
}

__device__ __forceinline__ void cluster_arrive_() {
    asm volatile("barrier.cluster.arrive.aligned;" ::: "memory");
}
__device__ __forceinline__ void cluster_wait_() {
    asm volatile("barrier.cluster.wait.aligned;" ::: "memory");
}

// overflow-safe fast sigmoid / tanh (MUFU-only)
__device__ __forceinline__ float sigmoid_(float x) {
    float e = __expf(-x);
    return __fdividef(1.0f, 1.0f + e);
}
__device__ __forceinline__ float tanh_(float x) {
    float e = __expf(2.0f * x);
    return 1.0f - __fdividef(2.0f, e + 1.0f);
}

__device__ __forceinline__ void mbar_init_(uint32_t addr, uint32_t cnt) {
    asm volatile("mbarrier.init.shared.b64 [%0], %1;" :: "r"(addr), "r"(cnt) : "memory");
}
__device__ __forceinline__ void mbar_arrive_expect_tx_(uint32_t addr, uint32_t bytes) {
    asm volatile("mbarrier.arrive.expect_tx.release.cta.shared::cta.b64 _, [%0], %1;"
                 :: "r"(addr), "r"(bytes) : "memory");
}
__device__ __forceinline__ void st_async_f32_(uint32_t dst, float v, uint32_t mbar) {
    asm volatile(
        "st.async.shared::cluster.mbarrier::complete_tx::bytes.f32 [%0], %1, [%2];"
        :: "r"(dst), "f"(v), "r"(mbar) : "memory");
}
__device__ __forceinline__ void bar_wait_(uint32_t mbar, uint32_t parity) {
    uint32_t done;
    asm volatile("{\n\t.reg .pred p;\n\t"
                 "mbarrier.try_wait.parity.acquire.cluster.shared::cta.b64 p, [%1], %2;\n\t"
                 "selp.b32 %0, 1, 0, p;\n\t}"
                 : "=r"(done) : "r"(mbar), "r"(parity) : "memory");
    while (!done) {
        asm volatile("{\n\t.reg .pred p;\n\t"
                     "mbarrier.try_wait.parity.acquire.cluster.shared::cta.b64 p, [%1], %2, 0x989680;\n\t"
                     "selp.b32 %0, 1, 0, p;\n\t}"
                     : "=r"(done) : "r"(mbar), "r"(parity) : "memory");
    }
}

// ---------------------------------------------------------------------------
// Kernel 1: xg = x @ W_i + bias    (M=65536, N=768, K=256)  fp32 tiled SGEMM
// Proven BM=128/BN=64/BK=16, 8x4 version (677us measured).
// ---------------------------------------------------------------------------
__global__ __launch_bounds__(256)
void gemm_xg_kernel(const float* __restrict__ X,
                    const float* __restrict__ Wi,
                    const float* __restrict__ bias)
{
    __shared__ __align__(16) float As[16][128];   // transposed A tile
    __shared__ __align__(16) float Bs[16][64];

    const int bm = blockIdx.x * 128;
    const int bn = blockIdx.y * 64;
    const int tid = threadIdx.x;
    const int tx = tid & 15;       // N direction (4 cols each)
    const int ty = tid >> 4;       // M direction (8 rows each)

    float acc[8][4];
#pragma unroll
    for (int i = 0; i < 8; ++i)
#pragma unroll
        for (int j = 0; j < 4; ++j) acc[i][j] = 0.0f;

    for (int k0 = 0; k0 < INDIM; k0 += 16) {
#pragma unroll
        for (int q = 0; q < 2; ++q) {
            int f   = q * 256 + tid;
            int row = f >> 2;
            int k4  = (f & 3) << 2;
            float4 v = *reinterpret_cast<const float4*>(
                X + (size_t)(bm + row) * INDIM + k0 + k4);
            As[k4 + 0][row] = v.x;
            As[k4 + 1][row] = v.y;
            As[k4 + 2][row] = v.z;
            As[k4 + 3][row] = v.w;
        }
        {
            int kr = tid >> 4;
            int c4 = (tid & 15) << 2;
            float4 v = *reinterpret_cast<const float4*>(
                Wi + (size_t)(k0 + kr) * GDIM + bn + c4);
            *reinterpret_cast<float4*>(&Bs[kr][c4]) = v;
        }
        __syncthreads();

#pragma unroll
        for (int kk = 0; kk < 16; ++kk) {
            float4 a0 = *reinterpret_cast<const float4*>(&As[kk][ty * 8]);
            float4 a1 = *reinterpret_cast<const float4*>(&As[kk][ty * 8 + 4]);
            float4 bv = *reinterpret_cast<const float4*>(&Bs[kk][tx * 4]);
            float a[8] = {a0.x, a0.y, a0.z, a0.w, a1.x, a1.y, a1.z, a1.w};
            float bb[4] = {bv.x, bv.y, bv.z, bv.w};
#pragma unroll
            for (int i = 0; i < 8; ++i)
#pragma unroll
                for (int j = 0; j < 4; ++j)
                    acc[i][j] = fmaf(a[i], bb[j], acc[i][j]);
        }
        __syncthreads();
    }

    float4 bv = *reinterpret_cast<const float4*>(bias + bn + tx * 4);
#pragma unroll
    for (int i = 0; i < 8; ++i) {
        int row = bm + ty * 8 + i;
        float4 o;
        o.x = acc[i][0] + bv.x;
        o.y = acc[i][1] + bv.y;
        o.z = acc[i][2] + bv.z;
        o.w = acc[i][3] + bv.w;
        *reinterpret_cast<float4*>(g_xg + (size_t)row * GDIM + bn + tx * 4) = o;
    }
}

// ---------------------------------------------------------------------------
// Kernel 2: GRU recurrence — per-chunk st.async protocol HARDENED with a
// 4-deep h-buffer ring: buffer t&3 is read at t, written at t-1, rewritten
// at t+3  =>  re-arm and WAR slack are 3 full steps (~6000 cyc), removing
// the two candidate hang mechanisms of the 2-buffer variant.
// Grid = 128 CTAs, cluster of 4 per batch row, 384 threads/CTA.
// tid = half*192 + col (half const per warp). Chunk c is produced by rank c;
// warps of half hf wait only on their 2 chunks (local chunk needs no wait).
// 16 barriers: bars[c][buf] at (c*4+buf)*8, expect_tx 256B per phase.
// Stateless parity: par(t) = (((t+3)>>2)+1)&1  (verified t=1..9).
// tid0 re-arms bars[c][t&3] (c != crank) after BAR#1 at each t>=1.
// ---------------------------------------------------------------------------
__global__ __launch_bounds__(384, 1) __cluster_dims__(4, 1, 1)
void gru_rec_kernel(const float* __restrict__ Wh,
                    float* __restrict__ states)
{
    __shared__ __align__(16) float h_sm[4][HDIM];   // ring: buf b at +b*1024B
    __shared__ __align__(16) float part[384];       // [half][col] raw partials
    __shared__ __align__(8) unsigned long long bars[16];  // [chunk][buf]

    uint32_t crank;
    asm("mov.u32 %0, %%cluster_ctarank;" : "=r"(crank));
    const int b    = blockIdx.x >> 2;
    const int tid  = threadIdx.x;
    const int half = tid / 192;       // K half, constant per warp
    const int col  = tid % 192;       // gate-column 0..191
    const int gate = col >> 6;        // 0..2
    const int jj   = col & 63;        // H index within chunk
    const int wcol = gate * HDIM + (int)crank * 64 + jj;   // W_h column

    // chunks my dot needs
    const int c0 = 2 * half, c1 = 2 * half + 1;
    const bool need0 = (c0 != (int)crank);
    const bool need1 = (c1 != (int)crank);

    // ---- W half-column in 128 regs ----
    float W[128];
    {
        const float* wp = Wh + (size_t)(half * 128) * GDIM + wcol;
#pragma unroll
        for (int e = 0; e < 128; ++e)
            W[e] = wp[(size_t)e * GDIM];
    }

    // ---- init: h ring (zero all 4), 16 barriers ----
    if (tid < HDIM) {
        h_sm[0][tid] = 0.0f; h_sm[1][tid] = 0.0f;
        h_sm[2][tid] = 0.0f; h_sm[3][tid] = 0.0f;
    }
    const uint32_t bars_base = smem_u32(&bars[0]);  // bars[c][bf] = +(c*4+bf)*8
    if (tid == 0) {
#pragma unroll
        for (int i = 0; i < 16; ++i) mbar_init_(bars_base + (uint32_t)i * 8u, 1);
#pragma unroll
        for (int c = 0; c < 4; ++c) {
            if (c != (int)crank) {
#pragma unroll
                for (int bf = 0; bf < 4; ++bf)
                    mbar_arrive_expect_tx_(bars_base + (uint32_t)(c * 4 + bf) * 8u, 256);
            }
        }
    }
    __syncthreads();
    cluster_arrive_();
    cluster_wait_();   // zeros + armed barriers visible cluster-wide

    // ---- my wait barrier bases (buf 0; buf bf = +bf*8) ----
    const uint32_t wbc0 = bars_base + (uint32_t)(c0 * 4) * 8u;
    const uint32_t wbc1 = bars_base + (uint32_t)(c1 * 4) * 8u;

    // ---- gate threads (tid<64): push targets in the 3 remote ranks ----
    uint32_t pdst0[3], pbar0[3];   // buf0 addresses; buf bf = dst+bf*1024 / bar+bf*8
    if (tid < 64) {
        uint32_t lh = smem_u32(&h_sm[0][(int)crank * 64 + tid]);
        int i = 0;
#pragma unroll
        for (int rk = 0; rk < 4; ++rk) {
            if (rk != (int)crank) {
                uint32_t rd, rb;
                asm("mapa.shared::cluster.u32 %0, %1, %2;" : "=r"(rd) : "r"(lh), "r"(rk));
                asm("mapa.shared::cluster.u32 %0, %1, %2;" : "=r"(rb) : "r"(bars_base), "r"(rk));
                pdst0[i] = rd;
                pbar0[i] = rb + crank * 32u;   // rank rk's bars[crank][0]
                ++i;
            }
        }
    }

    // ---- xg: 2-step-ahead register prefetch (gate threads) ----
    const float* xgp = g_xg + (size_t)b * TSTEPS * GDIM + (int)crank * 64 + (tid & 63);
    float x0r = 0.f, x0z = 0.f, x0n = 0.f;   // even t
    float x1r = 0.f, x1z = 0.f, x1n = 0.f;   // odd t
    if (tid < 64) {
        x0r = xgp[0];
        x0z = xgp[HDIM];
        x0n = xgp[2 * HDIM];
        const float* x1 = xgp + GDIM;
        x1r = x1[0];
        x1z = x1[HDIM];
        x1n = x1[2 * HDIM];
    }

    const size_t PL = (size_t)TSTEPS * HDIM;
    float* sp0 = states + (size_t)b * 4 * PL + (int)crank * 64 + (tid & 63);

    for (int t = 0; t < TSTEPS; ++t) {
        const int rb = t & 3;          // read buffer
        const int wbuf = (t + 1) & 3;  // write buffer
        const int cur = t & 1;         // xg ping-pong
        const bool last = (t == TSTEPS - 1);

        // ---- wait for my remote chunks (t=0 reads zeroed buf0) ----
        if (t > 0) {
            const uint32_t par = (uint32_t)((((t + 3) >> 2) + 1) & 1);
            const uint32_t boff = (uint32_t)rb * 8u;
            if (need0) bar_wait_(wbc0 + boff, par);
            if (need1) bar_wait_(wbc1 + boff, par);
        }

        // gate threads: h_old early (local chunk, ordered by BAR#2 of t-1)
        float h_old = 0.f;
        if (tid < 64) h_old = h_sm[rb][(int)crank * 64 + tid];

        // ---- dot over my K half (warp-broadcast LDS.128) ----
        const float4* hp = reinterpret_cast<const float4*>(&h_sm[rb][half * 128]);
        float a0 = 0.f, a1 = 0.f, a2 = 0.f, a3 = 0.f;
#pragma unroll
        for (int g = 0; g < 32; ++g) {
            float4 hv = hp[g];
            a0 = fmaf(W[g * 4 + 0], hv.x, a0);
            a1 = fmaf(W[g * 4 + 1], hv.y, a1);
            a2 = fmaf(W[g * 4 + 2], hv.z, a2);
            a3 = fmaf(W[g * 4 + 3], hv.w, a3);
        }
        part[half * 192 + col] = (a0 + a1) + (a2 + a3);

        __syncthreads();   // BAR#1: partials visible; all waits on rb done

        // tid0: re-arm bars[c][rb] (c != crank). Next bytes for these
        // barriers arrive from pushes at t+3 -> ~3 steps (~6000cyc) slack.
        if (t > 0 && tid == 0) {
            const uint32_t boff = (uint32_t)rb * 8u;
#pragma unroll
            for (int c = 0; c < 4; ++c)
                if (c != (int)crank)
                    mbar_arrive_expect_tx_(bars_base + (uint32_t)(c * 4) * 8u + boff, 256);
        }

        // ---- gates on 64 threads ----
        float r = 0.f, z = 0.f, n = 0.f, hn = 0.f;
        if (tid < 64) {
            float s0 = part[tid]        + part[192 + tid];
            float s1 = part[64 + tid]   + part[256 + tid];
            float s2 = part[128 + tid]  + part[320 + tid];
            float xr = cur ? x1r : x0r;
            float xz = cur ? x1z : x0z;
            float xn = cur ? x1n : x0n;
            r  = sigmoid_(xr + s0);
            z  = sigmoid_(xz + s1);
            float gg = xn + s2;
            n  = tanh_(fmaf(r, gg, gg));           // tanh(gn + r*gn)
            hn = fmaf(z, h_old - n, n);            // (1-z)n + z h

            if (!last) {
                h_sm[wbuf][(int)crank * 64 + tid] = hn;  // local chunk via STS
                const uint32_t doff = (uint32_t)wbuf * 1024u;
                const uint32_t soff = (uint32_t)wbuf * 8u;
#pragma unroll
                for (int i = 0; i < 3; ++i)
                    st_async_f32_(pdst0[i] + doff, hn, pbar0[i] + soff);
            }
        }

        // ---- off-chain: states STG + xg prefetch (t+2) ----
        if (tid < 64) {
            float* sp = sp0 + (size_t)t * HDIM;
            sp[0]      = hn;
            sp[PL]     = r;
            sp[2 * PL] = z;
            sp[3 * PL] = n;
            if (t + 2 < TSTEPS) {
                const float* xq = xgp + (size_t)(t + 2) * GDIM;
                if (cur) { x1r = xq[0]; x1z = xq[HDIM]; x1n = xq[2 * HDIM]; }
                else     { x0r = xq[0]; x0z = xq[HDIM]; x0n = xq[2 * HDIM]; }
            }
        }

        __syncthreads();   // BAR#2: local h STS visible; part[] WAR protected
    }
}

// ---------------------------------------------------------------------------
// Kernel 3: output = h_last @ fc_w + fc_b   (32 x 256, K=256) — tiny
// ---------------------------------------------------------------------------
__global__ __launch_bounds__(256)
void fc_kernel(const float* __restrict__ states,
               const float* __restrict__ fc_w,
               const float* __restrict__ fc_b,
               float* __restrict__ out)
{
    const int b = blockIdx.x;
    const int o = threadIdx.x;
    const float* h = states + (((size_t)b * 4 + 0) * TSTEPS + (TSTEPS - 1)) * HDIM;
    float a0 = 0.f, a1 = 0.f, a2 = 0.f, a3 = 0.f;
#pragma unroll 8
    for (int k = 0; k < HDIM; k += 4) {
        a0 = fmaf(h[k + 0], fc_w[(size_t)(k + 0) * OUTDIM + o], a0);
        a1 = fmaf(h[k + 1], fc_w[(size_t)(k + 1) * OUTDIM + o], a1);
        a2 = fmaf(h[k + 2], fc_w[(size_t)(k + 2) * OUTDIM + o], a2);
        a3 = fmaf(h[k + 3], fc_w[(size_t)(k + 3) * OUTDIM + o], a3);
    }
    out[(size_t)b * OUTDIM + o] = (a0 + a1) + (a2 + a3) + fc_b[o];
}

// ---------------------------------------------------------------------------
// Launch
// ---------------------------------------------------------------------------
extern "C" void kernel_launch(void* const* d_in, const int* in_sizes, int n_in,
                              void* d_out, int out_size)
{
    const float* x    = (const float*)d_in[0];
    const float* Wi   = (const float*)d_in[1];
    const float* Wh   = (const float*)d_in[2];
    const float* bias = (const float*)d_in[3];
    const float* fcw  = (const float*)d_in[4];
    const float* fcb  = (const float*)d_in[5];

    float* out    = (float*)d_out;                 // (32, 256)
    float* states = out + (size_t)BATCH * OUTDIM;  // (32, 4, 2048, 256)

    dim3 ggrid((BATCH * TSTEPS) / 128, GDIM / 64);
    gemm_xg_kernel<<<ggrid, 256>>>(x, Wi, bias);

    gru_rec_kernel<<<BATCH * 4, 384>>>(Wh, states);

    fc_kernel<<<BATCH, 256>>>(states, fcw, fcb, out);
}

// round 17
// speedup vs baseline: 1.1689x; 1.1689x over previous
#include <cuda_runtime.h>
#include <cuda_bf16.h>
#include <cstdint>
#include <cstddef>

// Problem constants
#define BATCH   32
#define TSTEPS  2048
#define INDIM   256
#define HDIM    256
#define GDIM    768            // 3*H
#define OUTDIM  256

// Scratch for xg = x @ W_i + bias : (B*T, 3H) fp32 = 192 MB
__device__ float g_xg[(size_t)BATCH * TSTEPS * GDIM];

// ---------------------------------------------------------------------------
// Helpers
// ---------------------------------------------------------------------------
__device__ __forceinline__ uint32_t smem_u32(const void* p) {
    uint32_t a;
    asm("{ .reg .u64 t; cvta.to.shared.u64 t, %1; cvt.u32.u64 %0, t; }"
        : "=r"(a) : "l"(p));
    return a;
}

__device__ __forceinline__ void cluster_arrive_() {
    asm volatile("barrier.cluster.arrive.aligned;" ::: "memory");
}
__device__ __forceinline__ void cluster_wait_() {
    asm volatile("barrier.cluster.wait.aligned;" ::: "memory");
}

// overflow-safe fast sigmoid / tanh (MUFU-only)
__device__ __forceinline__ float sigmoid_(float x) {
    float e = __expf(-x);
    return __fdividef(1.0f, 1.0f + e);
}
__device__ __forceinline__ float tanh_(float x) {
    float e = __expf(2.0f * x);
    return 1.0f - __fdividef(2.0f, e + 1.0f);
}

__device__ __forceinline__ void mbar_init_(uint32_t addr, uint32_t cnt) {
    asm volatile("mbarrier.init.shared.b64 [%0], %1;" :: "r"(addr), "r"(cnt) : "memory");
}
__device__ __forceinline__ void mbar_arrive_expect_tx_(uint32_t addr, uint32_t bytes) {
    asm volatile("mbarrier.arrive.expect_tx.release.cta.shared::cta.b64 _, [%0], %1;"
                 :: "r"(addr), "r"(bytes) : "memory");
}
__device__ __forceinline__ void st_async_f32_(uint32_t dst, float v, uint32_t mbar) {
    asm volatile(
        "st.async.shared::cluster.mbarrier::complete_tx::bytes.f32 [%0], %1, [%2];"
        :: "r"(dst), "f"(v), "r"(mbar) : "memory");
}
__device__ __forceinline__ void bar_wait_(uint32_t mbar, uint32_t parity) {
    uint32_t done;
    asm volatile("{\n\t.reg .pred p;\n\t"
                 "mbarrier.try_wait.parity.acquire.cluster.shared::cta.b64 p, [%1], %2;\n\t"
                 "selp.b32 %0, 1, 0, p;\n\t}"
                 : "=r"(done) : "r"(mbar), "r"(parity) : "memory");
    while (!done) {
        asm volatile("{\n\t.reg .pred p;\n\t"
                     "mbarrier.try_wait.parity.acquire.cluster.shared::cta.b64 p, [%1], %2, 0x989680;\n\t"
                     "selp.b32 %0, 1, 0, p;\n\t}"
                     : "=r"(done) : "r"(mbar), "r"(parity) : "memory");
    }
}

// ---------------------------------------------------------------------------
// Kernel 1: xg = x @ W_i + bias    (M=65536, N=768, K=256)  fp32 tiled SGEMM
// Proven BM=128/BN=64/BK=16, 8x4 version (677us measured).
// ---------------------------------------------------------------------------
__global__ __launch_bounds__(256)
void gemm_xg_kernel(const float* __restrict__ X,
                    const float* __restrict__ Wi,
                    const float* __restrict__ bias)
{
    __shared__ __align__(16) float As[16][128];   // transposed A tile
    __shared__ __align__(16) float Bs[16][64];

    const int bm = blockIdx.x * 128;
    const int bn = blockIdx.y * 64;
    const int tid = threadIdx.x;
    const int tx = tid & 15;       // N direction (4 cols each)
    const int ty = tid >> 4;       // M direction (8 rows each)

    float acc[8][4];
#pragma unroll
    for (int i = 0; i < 8; ++i)
#pragma unroll
        for (int j = 0; j < 4; ++j) acc[i][j] = 0.0f;

    for (int k0 = 0; k0 < INDIM; k0 += 16) {
#pragma unroll
        for (int q = 0; q < 2; ++q) {
            int f   = q * 256 + tid;
            int row = f >> 2;
            int k4  = (f & 3) << 2;
            float4 v = *reinterpret_cast<const float4*>(
                X + (size_t)(bm + row) * INDIM + k0 + k4);
            As[k4 + 0][row] = v.x;
            As[k4 + 1][row] = v.y;
            As[k4 + 2][row] = v.z;
            As[k4 + 3][row] = v.w;
        }
        {
            int kr = tid >> 4;
            int c4 = (tid & 15) << 2;
            float4 v = *reinterpret_cast<const float4*>(
                Wi + (size_t)(k0 + kr) * GDIM + bn + c4);
            *reinterpret_cast<float4*>(&Bs[kr][c4]) = v;
        }
        __syncthreads();

#pragma unroll
        for (int kk = 0; kk < 16; ++kk) {
            float4 a0 = *reinterpret_cast<const float4*>(&As[kk][ty * 8]);
            float4 a1 = *reinterpret_cast<const float4*>(&As[kk][ty * 8 + 4]);
            float4 bv = *reinterpret_cast<const float4*>(&Bs[kk][tx * 4]);
            float a[8] = {a0.x, a0.y, a0.z, a0.w, a1.x, a1.y, a1.z, a1.w};
            float bb[4] = {bv.x, bv.y, bv.z, bv.w};
#pragma unroll
            for (int i = 0; i < 8; ++i)
#pragma unroll
                for (int j = 0; j < 4; ++j)
                    acc[i][j] = fmaf(a[i], bb[j], acc[i][j]);
        }
        __syncthreads();
    }

    float4 bv = *reinterpret_cast<const float4*>(bias + bn + tx * 4);
#pragma unroll
    for (int i = 0; i < 8; ++i) {
        int row = bm + ty * 8 + i;
        float4 o;
        o.x = acc[i][0] + bv.x;
        o.y = acc[i][1] + bv.y;
        o.z = acc[i][2] + bv.z;
        o.w = acc[i][3] + bv.w;
        *reinterpret_cast<float4*>(g_xg + (size_t)row * GDIM + bn + tx * 4) = o;
    }
}

// ---------------------------------------------------------------------------
// Kernel 2: GRU recurrence — R12's proven whole-vector st.async mbarrier
// protocol (bars[2], count=1, expect_tx 1024B, re-arm after wait) with a
// BARRIER-FREE step: 512 threads, tid = j*8+ks; each thread owns all 3 gate
// columns of H-index crank*64+j over K slice [ks*32,+32) (W=96 regs, LDS
// rotation (gr+ks)&7 conflict-free). K-reduce = 9 in-warp shfl_xor; the 4
// gate lanes per warp then compute gates and st.async hn to ALL 4 ranks
// (incl. self) right after THEIR warp's dot — gates+fabric transit pipeline
// into other warps' FFMA issue. No __syncthreads in the loop; the 1024B tx
// ledger transitively orders every warp's reads before any buffer overwrite
// (each warp's pushes follow its full-mask shuffles).
// Grid = 128 CTAs, cluster of 4 per batch row.
// ---------------------------------------------------------------------------
__global__ __launch_bounds__(512, 1) __cluster_dims__(4, 1, 1)
void gru_rec_kernel(const float* __restrict__ Wh,
                    float* __restrict__ states)
{
    __shared__ __align__(16) float h_sm[2][HDIM];   // buf1 = buf0 + 1024B
    __shared__ __align__(8) unsigned long long bars[2];

    uint32_t crank;
    asm("mov.u32 %0, %%cluster_ctarank;" : "=r"(crank));
    const int b   = blockIdx.x >> 2;
    const int tid = threadIdx.x;
    const int j   = tid >> 3;       // H index within this CTA's 64-chunk
    const int ks  = tid & 7;        // K slice (32 wide), lane bits 0-2
    const int colbase = (int)crank * 64 + j;

    // ---- W: 3 gates x 32 K = 96 regs; granule order rotated by ks ----
    float W0[32], W1[32], W2[32];
    {
#pragma unroll
        for (int gr = 0; gr < 8; ++gr) {
            int rho = (gr + ks) & 7;
            int kbase = ks * 32 + rho * 4;
#pragma unroll
            for (int e = 0; e < 4; ++e) {
                const float* wr = Wh + (size_t)(kbase + e) * GDIM;
                W0[gr * 4 + e] = wr[colbase];
                W1[gr * 4 + e] = wr[HDIM + colbase];
                W2[gr * 4 + e] = wr[2 * HDIM + colbase];
            }
        }
    }

    // ---- init: h buffers, barriers (count=1, pre-armed both phases) ----
    if (tid < HDIM) { h_sm[0][tid] = 0.0f; h_sm[1][tid] = 0.0f; }
    const uint32_t bar_l0 = smem_u32(&bars[0]);    // bars[1] = +8B
    if (tid == 0) {
        mbar_init_(bar_l0, 1);
        mbar_init_(bar_l0 + 8u, 1);
        mbar_arrive_expect_tx_(bar_l0, 1024);       // arm first use of buf0
        mbar_arrive_expect_tx_(bar_l0 + 8u, 1024);  // arm first use of buf1
    }
    __syncthreads();
    cluster_arrive_();
    cluster_wait_();   // zeros + armed barriers visible cluster-wide

    // local addresses for inline mapa in the push loop
    const uint32_t lh = smem_u32(&h_sm[0][colbase]);   // my h slot, buf0

    // ---- xg: 2-step-ahead register prefetch (gate lanes ks==0) ----
    const float* xgp = g_xg + (size_t)b * TSTEPS * GDIM + colbase;
    float x0r = 0.f, x0z = 0.f, x0n = 0.f;   // even t
    float x1r = 0.f, x1z = 0.f, x1n = 0.f;   // odd t
    if (ks == 0) {
        x0r = xgp[0];
        x0z = xgp[HDIM];
        x0n = xgp[2 * HDIM];
        const float* x1 = xgp + GDIM;
        x1r = x1[0];
        x1z = x1[HDIM];
        x1n = x1[2 * HDIM];
    }

    const size_t PL = (size_t)TSTEPS * HDIM;
    float* sp0 = states + (size_t)b * 4 * PL + colbase;

    int ph0 = 0, ph1 = 0;   // parity per buffer barrier

    for (int t = 0; t < TSTEPS; ++t) {
        const int cur = t & 1;
        const int nxt = cur ^ 1;
        const bool last = (t == TSTEPS - 1);

        // gate lanes: h_old early
        float h_old = 0.f;
        if (ks == 0) h_old = h_sm[cur][colbase];

        // ---- 3 dots of length 32 (rotated conflict-free LDS.128) ----
        const float4* hp = reinterpret_cast<const float4*>(&h_sm[cur][ks * 32]);
        float a0 = 0.f, a1 = 0.f, a2 = 0.f;
        float b0 = 0.f, b1 = 0.f, b2 = 0.f;
#pragma unroll
        for (int gr = 0; gr < 8; ++gr) {
            int rho = (gr + ks) & 7;
            float4 hv = hp[rho];
            a0 = fmaf(W0[gr * 4 + 0], hv.x, a0);
            a1 = fmaf(W1[gr * 4 + 0], hv.x, a1);
            a2 = fmaf(W2[gr * 4 + 0], hv.x, a2);
            b0 = fmaf(W0[gr * 4 + 1], hv.y, b0);
            b1 = fmaf(W1[gr * 4 + 1], hv.y, b1);
            b2 = fmaf(W2[gr * 4 + 1], hv.y, b2);
            a0 = fmaf(W0[gr * 4 + 2], hv.z, a0);
            a1 = fmaf(W1[gr * 4 + 2], hv.z, a1);
            a2 = fmaf(W2[gr * 4 + 2], hv.z, a2);
            b0 = fmaf(W0[gr * 4 + 3], hv.w, b0);
            b1 = fmaf(W1[gr * 4 + 3], hv.w, b1);
            b2 = fmaf(W2[gr * 4 + 3], hv.w, b2);
        }
        float s0 = a0 + b0, s1 = a1 + b1, s2 = a2 + b2;
        // in-warp K-reduce across the 8 slices (lane bits 0-2); full-mask
        // shuffles also order this warp's h reads before its pushes below
        s0 += __shfl_xor_sync(0xffffffffu, s0, 1);
        s1 += __shfl_xor_sync(0xffffffffu, s1, 1);
        s2 += __shfl_xor_sync(0xffffffffu, s2, 1);
        s0 += __shfl_xor_sync(0xffffffffu, s0, 2);
        s1 += __shfl_xor_sync(0xffffffffu, s1, 2);
        s2 += __shfl_xor_sync(0xffffffffu, s2, 2);
        s0 += __shfl_xor_sync(0xffffffffu, s0, 4);
        s1 += __shfl_xor_sync(0xffffffffu, s1, 4);
        s2 += __shfl_xor_sync(0xffffffffu, s2, 4);

        // ---- gate lanes: gates + st.async to all 4 ranks (incl. self) ----
        float r = 0.f, z = 0.f, n = 0.f, hn = 0.f;
        if (ks == 0) {
            float xr = cur ? x1r : x0r;
            float xz = cur ? x1z : x0z;
            float xn = cur ? x1n : x0n;
            r  = sigmoid_(xr + s0);
            z  = sigmoid_(xz + s1);
            float gg = xn + s2;
            n  = tanh_(fmaf(r, gg, gg));           // tanh(gn + r*gn)
            hn = fmaf(z, h_old - n, n);            // (1-z)n + z h

            if (!last) {
                const uint32_t doff = (uint32_t)nxt * 1024u;
                const uint32_t soff = (uint32_t)nxt * 8u;
#pragma unroll
                for (int rk = 0; rk < 4; ++rk) {
                    uint32_t rd, rbb;
                    asm("mapa.shared::cluster.u32 %0, %1, %2;"
                        : "=r"(rd) : "r"(lh), "r"(rk));
                    asm("mapa.shared::cluster.u32 %0, %1, %2;"
                        : "=r"(rbb) : "r"(bar_l0), "r"(rk));
                    st_async_f32_(rd + doff, hn, rbb + soff);
                }
            }
        }

        // ---- overlapped with transit: states STG + xg prefetch (t+2) ----
        if (ks == 0) {
            float* sp = sp0 + (size_t)t * HDIM;
            sp[0]      = hn;
            sp[PL]     = r;
            sp[2 * PL] = z;
            sp[3 * PL] = n;
            if (t + 2 < TSTEPS) {
                const float* xq = xgp + (size_t)(t + 2) * GDIM;
                if (cur) { x1r = xq[0]; x1z = xq[HDIM]; x1n = xq[2 * HDIM]; }
                else     { x0r = xq[0]; x0z = xq[HDIM]; x0n = xq[2 * HDIM]; }
            }
        }

        if (!last) {
            // wait for all 1024B (4 CTAs x 64 gate lanes) on buffer nxt
            if (nxt) { bar_wait_(bar_l0 + 8u, (uint32_t)ph1); ph1 ^= 1; }
            else     { bar_wait_(bar_l0,      (uint32_t)ph0); ph0 ^= 1; }
            // re-arm this barrier for its use 2 steps ahead (sole arrival)
            if (tid == 0) mbar_arrive_expect_tx_(bar_l0 + (uint32_t)nxt * 8u, 1024);
        }
    }
}

// ---------------------------------------------------------------------------
// Kernel 3: output = h_last @ fc_w + fc_b   (32 x 256, K=256) — tiny
// ---------------------------------------------------------------------------
__global__ __launch_bounds__(256)
void fc_kernel(const float* __restrict__ states,
               const float* __restrict__ fc_w,
               const float* __restrict__ fc_b,
               float* __restrict__ out)
{
    const int b = blockIdx.x;
    const int o = threadIdx.x;
    const float* h = states + (((size_t)b * 4 + 0) * TSTEPS + (TSTEPS - 1)) * HDIM;
    float a0 = 0.f, a1 = 0.f, a2 = 0.f, a3 = 0.f;
#pragma unroll 8
    for (int k = 0; k < HDIM; k += 4) {
        a0 = fmaf(h[k + 0], fc_w[(size_t)(k + 0) * OUTDIM + o], a0);
        a1 = fmaf(h[k + 1], fc_w[(size_t)(k + 1) * OUTDIM + o], a1);
        a2 = fmaf(h[k + 2], fc_w[(size_t)(k + 2) * OUTDIM + o], a2);
        a3 = fmaf(h[k + 3], fc_w[(size_t)(k + 3) * OUTDIM + o], a3);
    }
    out[(size_t)b * OUTDIM + o] = (a0 + a1) + (a2 + a3) + fc_b[o];
}

// ---------------------------------------------------------------------------
// Launch
// ---------------------------------------------------------------------------
extern "C" void kernel_launch(void* const* d_in, const int* in_sizes, int n_in,
                              void* d_out, int out_size)
{
    const float* x    = (const float*)d_in[0];
    const float* Wi   = (const float*)d_in[1];
    const float* Wh   = (const float*)d_in[2];
    const float* bias = (const float*)d_in[3];
    const float* fcw  = (const float*)d_in[4];
    const float* fcb  = (const float*)d_in[5];

    float* out    = (float*)d_out;                 // (32, 256)
    float* states = out + (size_t)BATCH * OUTDIM;  // (32, 4, 2048, 256)

    dim3 ggrid((BATCH * TSTEPS) / 128, GDIM / 64);
    gemm_xg_kernel<<<ggrid, 256>>>(x, Wi, bias);

    gru_rec_kernel<<<BATCH * 4, 512>>>(Wh, states);

    fc_kernel<<<BATCH, 256>>>(states, fcw, fcb, out);
}